// round 5
// baseline (speedup 1.0000x reference)
#include <cuda_runtime.h>
#include <cuda_bf16.h>
#include <cstdint>

// OctreeMaxUnpool:
//   out[(i*8 + c)*C + k] = (indices[i*C + k] == c) ? data[nempty_idx[i]*C + k] : 0
//
// R5: one warp per 4 consecutive rows (C=64).
//  - Loads front-batched: 4 data float4s + 4 index int4s per thread (8
//    independent LDG.128 in flight) + one uniform int4 of nempty_idx.
//  - Stores: 16 STG.128 per warp covering 8192 fully contiguous ascending
//    bytes (4 rows x 2048 B) — maximal same-direction write bursts.
//  Thread t stores child slots (t>>4)+2j at float4-lane (t&15) for each row.

#define NUM_CHILDREN 8

__device__ __forceinline__ float4 child_select(int4 ix, float4 d, int c) {
    float4 o;
    o.x = (ix.x == c) ? d.x : 0.0f;
    o.y = (ix.y == c) ? d.y : 0.0f;
    o.z = (ix.z == c) ? d.z : 0.0f;
    o.w = (ix.w == c) ? d.w : 0.0f;
    return o;
}

// C = 64 fast path: one warp per 4 rows. num is padded-checked per row.
__global__ void __launch_bounds__(256)
octree_unpool_warp4_kernel(const float4* __restrict__ data,
                           const int4*  __restrict__ indices,
                           const int*   __restrict__ nempty_idx,
                           float4*      __restrict__ out,
                           int num)
{
    constexpr int C4 = 16;                        // float4 lanes per row
    int gtid = blockIdx.x * blockDim.x + threadIdx.x;
    int w    = gtid >> 5;                         // warp id
    int t    = gtid & 31;                         // lane in warp
    int i0   = w * 4;                             // first row of this warp
    if (i0 >= num) return;

    int l = t & 15;                               // float4 lane within row
    int h = t >> 4;                               // half-warp id (0/1)

    bool full = (i0 + 4 <= num);

    if (full) {
        // Uniform load of 4 consecutive source indices.
        int4 srcs = __ldg((const int4*)(nempty_idx + i0));

        // Front-batched independent loads: 4 data + 4 index vectors.
        float4 d0 = __ldg(&data[(long long)srcs.x * C4 + l]);
        float4 d1 = __ldg(&data[(long long)srcs.y * C4 + l]);
        float4 d2 = __ldg(&data[(long long)srcs.z * C4 + l]);
        float4 d3 = __ldg(&data[(long long)srcs.w * C4 + l]);
        int4 x0 = __ldg(&indices[(long long)(i0 + 0) * C4 + l]);
        int4 x1 = __ldg(&indices[(long long)(i0 + 1) * C4 + l]);
        int4 x2 = __ldg(&indices[(long long)(i0 + 2) * C4 + l]);
        int4 x3 = __ldg(&indices[(long long)(i0 + 3) * C4 + l]);

        float4* base = out + (long long)i0 * (NUM_CHILDREN * C4);
#pragma unroll
        for (int j = 0; j < 4; j++) {
            int c = h + 2 * j;                    // child slot this thread writes
            // row r position = r*128 + c*16 + l = r*128 + t + 32*j (ascending)
            __stcs(base +   0 + t + 32 * j, child_select(x0, d0, c));
            __stcs(base + 128 + t + 32 * j, child_select(x1, d1, c));
            __stcs(base + 256 + t + 32 * j, child_select(x2, d2, c));
            __stcs(base + 384 + t + 32 * j, child_select(x3, d3, c));
        }
    } else {
        // Tail: per-row handling.
        for (int i = i0; i < num; i++) {
            int src = __ldg(&nempty_idx[i]);
            float4 d  = __ldg(&data[(long long)src * C4 + l]);
            int4   ix = __ldg(&indices[(long long)i * C4 + l]);
            float4* rowbase = out + (long long)i * (NUM_CHILDREN * C4);
#pragma unroll
            for (int j = 0; j < 4; j++) {
                int c = h + 2 * j;
                __stcs(rowbase + t + 32 * j, child_select(ix, d, c));
            }
        }
    }
}

// Generic-C vectorized kernel (runtime C4) for C % 4 == 0 but C != 64.
__global__ void __launch_bounds__(256)
octree_unpool_vec_dyn_kernel(const float4* __restrict__ data,
                             const int4*  __restrict__ indices,
                             const int*   __restrict__ nempty_idx,
                             float4*      __restrict__ out,
                             int num, int C4)
{
    int gtid = blockIdx.x * blockDim.x + threadIdx.x;
    int i    = gtid / C4;
    int lane = gtid - i * C4;
    if (i >= num) return;

    int src = __ldg(&nempty_idx[i]);
    float4 d  = __ldg(&data[(long long)src * C4 + lane]);
    int4   ix = __ldg(&indices[(long long)i * C4 + lane]);

    long long base = (long long)i * (NUM_CHILDREN * C4) + lane;
#pragma unroll
    for (int c = 0; c < NUM_CHILDREN; c++) {
        out[base + (long long)c * C4] = child_select(ix, d, c);
    }
}

// Scalar fallback for arbitrary C.
__global__ void __launch_bounds__(256)
octree_unpool_scalar_kernel(const float* __restrict__ data,
                            const int*   __restrict__ indices,
                            const int*   __restrict__ nempty_idx,
                            float*       __restrict__ out,
                            int num, int C)
{
    long long gtid = (long long)blockIdx.x * blockDim.x + threadIdx.x;
    long long total = (long long)num * C;
    if (gtid >= total) return;
    int i = (int)(gtid / C);
    int k = (int)(gtid - (long long)i * C);

    int src  = __ldg(&nempty_idx[i]);
    float dv = __ldg(&data[(long long)src * C + k]);
    int   ix = __ldg(&indices[(long long)i * C + k]);

    long long base = ((long long)i * NUM_CHILDREN) * C + k;
#pragma unroll
    for (int c = 0; c < NUM_CHILDREN; c++) {
        out[base + (long long)c * C] = (ix == c) ? dv : 0.0f;
    }
}

extern "C" void kernel_launch(void* const* d_in, const int* in_sizes, int n_in,
                              void* d_out, int out_size)
{
    const float* data       = (const float*)d_in[0];
    const int*   indices    = (const int*)d_in[1];
    const int*   nempty_idx = (const int*)d_in[2];
    // d_in[3] = depth (unused: the gather is already expressed by nempty_idx)

    float* out = (float*)d_out;

    int num = in_sizes[2];
    int C   = (num > 0) ? (in_sizes[1] / num) : 0;

    if (num <= 0 || C <= 0) return;

    if (C == 64 && (num % 4 == 0 || num >= 4)) {
        int rows4 = (num + 3) / 4;                 // warps needed
        long long threads = (long long)rows4 * 32;
        int block = 256;
        int grid  = (int)((threads + block - 1) / block);
        octree_unpool_warp4_kernel<<<grid, block>>>(
            (const float4*)data, (const int4*)indices, nempty_idx,
            (float4*)out, num);
    } else if ((C & 3) == 0) {
        int C4 = C >> 2;
        long long threads = (long long)num * C4;
        int block = 256;
        int grid  = (int)((threads + block - 1) / block);
        octree_unpool_vec_dyn_kernel<<<grid, block>>>(
            (const float4*)data, (const int4*)indices, nempty_idx,
            (float4*)out, num, C4);
    } else {
        long long threads = (long long)num * C;
        int block = 256;
        int grid  = (int)((threads + block - 1) / block);
        octree_unpool_scalar_kernel<<<grid, block>>>(
            data, indices, nempty_idx, out, num, C);
    }
}

// round 6
// speedup vs baseline: 1.1023x; 1.1023x over previous
#include <cuda_runtime.h>
#include <cuda_bf16.h>
#include <cstdint>

// OctreeMaxUnpool:
//   out[(i*8 + c)*C + k] = (indices[i*C + k] == c) ? data[nempty_idx[i]*C + k] : 0
//
// R6 = R4 (best: 183.0 us, DRAM 82.5%) + streaming-read hints on the
// read-once inputs:
//   - indices (128 MB, read exactly once)  -> __ldcs (evict-first)
//   - nempty_idx (2 MB, read once)         -> __ldcs
//   - data (has ~32% row reuse)            -> __ldg  (keep cached)
// Layout unchanged: one warp per row; every STG.128 instruction writes 512
// fully contiguous ascending bytes; 4 stores cover the row's 2048-B span.
// Stores stay __stcs (write-once output, full-line-per-instruction pattern).

#define NUM_CHILDREN 8

__device__ __forceinline__ float4 child_select(int4 ix, float4 d, int c) {
    float4 o;
    o.x = (ix.x == c) ? d.x : 0.0f;
    o.y = (ix.y == c) ? d.y : 0.0f;
    o.z = (ix.z == c) ? d.z : 0.0f;
    o.w = (ix.w == c) ? d.w : 0.0f;
    return o;
}

// C = 64 fast path: one warp per row.
__global__ void __launch_bounds__(256)
octree_unpool_warprow_kernel(const float4* __restrict__ data,
                             const int4*  __restrict__ indices,
                             const int*   __restrict__ nempty_idx,
                             float4*      __restrict__ out,
                             int num)
{
    constexpr int C4 = 16;                       // float4 lanes per row
    int gtid = blockIdx.x * blockDim.x + threadIdx.x;
    int i    = gtid >> 5;                        // row = warp id
    int t    = gtid & 31;                        // lane in warp
    if (i >= num) return;

    int l = t & 15;                              // float4 lane within row
    int h = t >> 4;                              // half-warp id (0/1)

    int src = __ldcs(&nempty_idx[i]);            // read-once: evict-first
    float4 d  = __ldg(&data[(long long)src * C4 + l]);      // reused: cached
    int4   ix = __ldcs(&indices[(long long)i * C4 + l]);    // read-once

    float4* rowbase = out + (long long)i * (NUM_CHILDREN * C4);
#pragma unroll
    for (int j = 0; j < 4; j++) {
        int c = h + 2 * j;                       // child slot this thread writes
        float4 o = child_select(ix, d, c);
        // position within row = c*16 + l = t + 32*j  (ascending contiguous)
        __stcs(rowbase + t + 32 * j, o);
    }
}

// Generic-C vectorized kernel (runtime C4) for C % 4 == 0 but C != 64.
__global__ void __launch_bounds__(256)
octree_unpool_vec_dyn_kernel(const float4* __restrict__ data,
                             const int4*  __restrict__ indices,
                             const int*   __restrict__ nempty_idx,
                             float4*      __restrict__ out,
                             int num, int C4)
{
    int gtid = blockIdx.x * blockDim.x + threadIdx.x;
    int i    = gtid / C4;
    int lane = gtid - i * C4;
    if (i >= num) return;

    int src = __ldcs(&nempty_idx[i]);
    float4 d  = __ldg(&data[(long long)src * C4 + lane]);
    int4   ix = __ldcs(&indices[(long long)i * C4 + lane]);

    long long base = (long long)i * (NUM_CHILDREN * C4) + lane;
#pragma unroll
    for (int c = 0; c < NUM_CHILDREN; c++) {
        out[base + (long long)c * C4] = child_select(ix, d, c);
    }
}

// Scalar fallback for arbitrary C.
__global__ void __launch_bounds__(256)
octree_unpool_scalar_kernel(const float* __restrict__ data,
                            const int*   __restrict__ indices,
                            const int*   __restrict__ nempty_idx,
                            float*       __restrict__ out,
                            int num, int C)
{
    long long gtid = (long long)blockIdx.x * blockDim.x + threadIdx.x;
    long long total = (long long)num * C;
    if (gtid >= total) return;
    int i = (int)(gtid / C);
    int k = (int)(gtid - (long long)i * C);

    int src  = __ldcs(&nempty_idx[i]);
    float dv = __ldg(&data[(long long)src * C + k]);
    int   ix = __ldcs(&indices[(long long)i * C + k]);

    long long base = ((long long)i * NUM_CHILDREN) * C + k;
#pragma unroll
    for (int c = 0; c < NUM_CHILDREN; c++) {
        out[base + (long long)c * C] = (ix == c) ? dv : 0.0f;
    }
}

extern "C" void kernel_launch(void* const* d_in, const int* in_sizes, int n_in,
                              void* d_out, int out_size)
{
    const float* data       = (const float*)d_in[0];
    const int*   indices    = (const int*)d_in[1];
    const int*   nempty_idx = (const int*)d_in[2];
    // d_in[3] = depth (unused: the gather is already expressed by nempty_idx)

    float* out = (float*)d_out;

    int num = in_sizes[2];
    int C   = (num > 0) ? (in_sizes[1] / num) : 0;

    if (num <= 0 || C <= 0) return;

    if (C == 64) {
        long long threads = (long long)num * 32;   // one warp per row
        int block = 256;
        int grid  = (int)((threads + block - 1) / block);
        octree_unpool_warprow_kernel<<<grid, block>>>(
            (const float4*)data, (const int4*)indices, nempty_idx,
            (float4*)out, num);
    } else if ((C & 3) == 0) {
        int C4 = C >> 2;
        long long threads = (long long)num * C4;
        int block = 256;
        int grid  = (int)((threads + block - 1) / block);
        octree_unpool_vec_dyn_kernel<<<grid, block>>>(
            (const float4*)data, (const int4*)indices, nempty_idx,
            (float4*)out, num, C4);
    } else {
        long long threads = (long long)num * C;
        int block = 256;
        int grid  = (int)((threads + block - 1) / block);
        octree_unpool_scalar_kernel<<<grid, block>>>(
            data, indices, nempty_idx, out, num, C);
    }
}